// round 11
// baseline (speedup 1.0000x reference)
#include <cuda_runtime.h>
#include <cuda_fp16.h>
#include <cstdint>

#define NN 50000
#define EE 1600000
#define CC 128
#define NG 128
#define SB 1024
#define NBK ((NN + SB - 1) / SB)   // 49

// ---- scratch (static device globals) ----
__device__ uint2  s_Hh [NN * 32];    // H  fp16: 128 halves/row
__device__ uint2  s_P0h[NN * 32];    // layer out fp16 (relu applied)
__device__ uint2  s_P1h[NN * 32];
__device__ __half s_W1h[CC * CC];
__device__ __half s_W2h[CC * CC];
__device__ float  s_dinv[NN];
__device__ int    s_deg [NN];
__device__ int    s_rowptr[NN + 1];
__device__ int    s_cursor[NN];
__device__ int2   s_edge [EE];       // {src, coef bits}
__device__ int    s_pref [NBK];      // chained-scan prefixes (-1 = not ready)
__device__ float  s_gacc [NG];       // pooled dot accumulators

// ============ init: zero deg/sentinels/gacc, convert W ============
__global__ void init_k(const float* __restrict__ W1, const float* __restrict__ W2) {
    int i = blockIdx.x * blockDim.x + threadIdx.x;
    if (i < NN) s_deg[i] = 0;
    if (i < NBK) s_pref[i] = -1;
    if (i < NG) s_gacc[i] = 0.f;
    if (i < CC * CC) {
        s_W1h[i] = __float2half(W1[i]);
        s_W2h[i] = __float2half(W2[i]);
    }
}

__global__ void deg_k(const int* __restrict__ ei) {
    int e = blockIdx.x * blockDim.x + threadIdx.x;
    if (e < EE) atomicAdd(&s_deg[ei[EE + e]], 1);
}

// ============ fused chained scan: rowptr/cursor/dinv in ONE kernel ============
__global__ void scanf_k() {
    const int tid  = threadIdx.x;
    const int lane = tid & 31;
    const int wid  = tid >> 5;
    const int bid  = blockIdx.x;
    const int i    = bid * SB + tid;
    int v = (i < NN) ? s_deg[i] : 0;

    int x = v;
    #pragma unroll
    for (int o = 1; o < 32; o <<= 1) {
        int t = __shfl_up_sync(0xffffffffu, x, o);
        if (lane >= o) x += t;
    }
    __shared__ int wsum[32];
    if (lane == 31) wsum[wid] = x;
    __syncthreads();
    if (wid == 0) {
        int s = wsum[lane];
        #pragma unroll
        for (int o = 1; o < 32; o <<= 1) {
            int t = __shfl_up_sync(0xffffffffu, s, o);
            if (lane >= o) s += t;
        }
        wsum[lane] = s;
    }
    __syncthreads();
    int incl  = x + (wid ? wsum[wid - 1] : 0);
    int total = wsum[31];

    __shared__ int sprev;
    if (tid == 0) {
        int prev = 0;
        if (bid > 0)
            while ((prev = atomicAdd(&s_pref[bid - 1], 0)) < 0) {}
        sprev = prev;
        __threadfence();
        atomicExch(&s_pref[bid], prev + total);
    }
    __syncthreads();
    int base = sprev;

    if (i < NN) {
        int ex = base + incl - v;
        s_rowptr[i] = ex;
        s_cursor[i] = ex;
        s_dinv[i]   = rsqrtf((float)s_deg[i] + 1.0f);
    }
    if (i == 0) s_rowptr[NN] = EE;
}

// counting-sort by dst; pack {src, coef}
__global__ void build_k(const int* __restrict__ ei) {
    int e = blockIdx.x * blockDim.x + threadIdx.x;
    if (e >= EE) return;
    int src = ei[e];
    int dst = ei[EE + e];
    int slot = atomicAdd(&s_cursor[dst], 1);
    float coef = s_dinv[src] * s_dinv[dst];
    s_edge[slot] = make_int2(src, __float_as_int(coef));
}

// ============ tensor-core GEMM: H(fp16) = A @ W ============
__device__ __forceinline__ unsigned swz(unsigned row, unsigned col_half) {
    unsigned b = row * 256u + col_half * 2u;
    return b ^ ((row & 7u) << 4);
}

template<int SRC>
__global__ void __launch_bounds__(256) gemm_tc_k(const float* __restrict__ X,
                                                 const __half* __restrict__ Wh) {
    __shared__ __align__(16) unsigned char smem[49152];   // A: 16KB, W: 32KB
    const unsigned sb  = (unsigned)__cvta_generic_to_shared(smem);
    const unsigned sbA = sb;
    const unsigned sbW = sb + 16384u;
    const int tid  = threadIdx.x;
    const int row0 = blockIdx.x * 64;

    if (SRC == 0) {
        #pragma unroll
        for (int it = 0; it < 4; it++) {
            int idx = it * 256 + tid;
            int r   = idx >> 4;
            int c16 = idx & 15;
            int gr  = row0 + r;
            uint4 o;
            if (gr < NN) {
                const float4* p = (const float4*)(X + (size_t)gr * CC + c16 * 8);
                float4 f0 = p[0], f1 = p[1];
                __half2 h0 = __floats2half2_rn(f0.x, f0.y);
                __half2 h1 = __floats2half2_rn(f0.z, f0.w);
                __half2 h2 = __floats2half2_rn(f1.x, f1.y);
                __half2 h3 = __floats2half2_rn(f1.z, f1.w);
                o.x = *(unsigned*)&h0; o.y = *(unsigned*)&h1;
                o.z = *(unsigned*)&h2; o.w = *(unsigned*)&h3;
            } else {
                o = make_uint4(0u, 0u, 0u, 0u);
            }
            *(uint4*)(smem + swz((unsigned)r, (unsigned)(c16 * 8))) = o;
        }
    } else {
        const __half* P = (SRC == 1) ? (const __half*)s_P0h : (const __half*)s_P1h;
        #pragma unroll
        for (int it = 0; it < 4; it++) {
            int idx = it * 256 + tid;
            int r   = idx >> 4;
            int c16 = idx & 15;
            int gr  = row0 + r;
            uint4 o = make_uint4(0u, 0u, 0u, 0u);
            if (gr < NN) o = *(const uint4*)(P + (size_t)gr * CC + c16 * 8);
            *(uint4*)(smem + swz((unsigned)r, (unsigned)(c16 * 8))) = o;
        }
    }
    #pragma unroll
    for (int it = 0; it < 8; it++) {
        int idx = it * 256 + tid;
        int r   = idx >> 4;
        int c16 = idx & 15;
        uint4 o = *(const uint4*)(Wh + (size_t)r * CC + c16 * 8);
        *(uint4*)(smem + 16384 + swz((unsigned)r, (unsigned)(c16 * 8))) = o;
    }
    __syncthreads();

    const int warp   = tid >> 5;
    const int lane   = tid & 31;
    const int warp_m = warp & 3;
    const int warp_n = warp >> 2;
    const int rloc   = warp_m * 16;
    const int c0     = warp_n * 64;

    float d[8][4];
    #pragma unroll
    for (int i = 0; i < 8; i++)
        #pragma unroll
        for (int j = 0; j < 4; j++) d[i][j] = 0.f;

    const int fr = (lane & 7) + ((lane >> 3) & 1) * 8;
    const int fc = (lane >> 4) * 8;

    #pragma unroll
    for (int ks = 0; ks < 8; ks++) {
        const int k0 = ks * 16;
        unsigned a0, a1, a2, a3;
        {
            unsigned addrA = sbA + swz((unsigned)(rloc + fr), (unsigned)(k0 + fc));
            asm volatile("ldmatrix.sync.aligned.m8n8.x4.shared.b16 {%0,%1,%2,%3}, [%4];"
                         : "=r"(a0), "=r"(a1), "=r"(a2), "=r"(a3) : "r"(addrA));
        }
        #pragma unroll
        for (int q = 0; q < 4; q++) {
            int n0 = c0 + q * 16;
            unsigned b0, b1, b2, b3;
            unsigned addrB = sbW + swz((unsigned)(k0 + fr), (unsigned)(n0 + fc));
            asm volatile("ldmatrix.sync.aligned.m8n8.x4.trans.shared.b16 {%0,%1,%2,%3}, [%4];"
                         : "=r"(b0), "=r"(b1), "=r"(b2), "=r"(b3) : "r"(addrB));
            asm volatile("mma.sync.aligned.m16n8k16.row.col.f32.f16.f16.f32 "
                         "{%0,%1,%2,%3}, {%4,%5,%6,%7}, {%8,%9}, {%0,%1,%2,%3};"
                         : "+f"(d[q*2][0]), "+f"(d[q*2][1]), "+f"(d[q*2][2]), "+f"(d[q*2][3])
                         : "r"(a0), "r"(a1), "r"(a2), "r"(a3), "r"(b0), "r"(b1));
            asm volatile("mma.sync.aligned.m16n8k16.row.col.f32.f16.f16.f32 "
                         "{%0,%1,%2,%3}, {%4,%5,%6,%7}, {%8,%9}, {%0,%1,%2,%3};"
                         : "+f"(d[q*2+1][0]), "+f"(d[q*2+1][1]), "+f"(d[q*2+1][2]), "+f"(d[q*2+1][3])
                         : "r"(a0), "r"(a1), "r"(a2), "r"(a3), "r"(b2), "r"(b3));
        }
    }

    __half* H = (__half*)s_Hh;
    const int g  = lane >> 2;
    const int cq = (lane & 3) * 2;
    const int ra = row0 + rloc + g;
    const int rb = ra + 8;
    #pragma unroll
    for (int nt = 0; nt < 8; nt++) {
        int col = c0 + nt * 8 + cq;
        if (ra < NN) *(__half2*)(H + (size_t)ra * CC + col) = __floats2half2_rn(d[nt][0], d[nt][1]);
        if (rb < NN) *(__half2*)(H + (size_t)rb * CC + col) = __floats2half2_rn(d[nt][2], d[nt][3]);
    }
}

// shared gather body: returns relu-ready accumulator (pre-relu)
__device__ __forceinline__ float4 agg_body(int node, int lane, const float* __restrict__ b) {
    float di = s_dinv[node];
    float sc = di * di;

    uint2 hs = s_Hh[(size_t)node * 32 + lane];
    float2 h01 = __half22float2(*(__half2*)&hs.x);
    float2 h23 = __half22float2(*(__half2*)&hs.y);
    float4 acc;
    acc.x = fmaf(h01.x, sc, b[lane * 4 + 0]);
    acc.y = fmaf(h01.y, sc, b[lane * 4 + 1]);
    acc.z = fmaf(h23.x, sc, b[lane * 4 + 2]);
    acc.w = fmaf(h23.y, sc, b[lane * 4 + 3]);

    const int beg = s_rowptr[node];
    const int end = s_rowptr[node + 1];
    int e = beg;
    for (; e + 4 <= end; e += 4) {
        int2 e0 = s_edge[e],   e1 = s_edge[e+1], e2 = s_edge[e+2], e3 = s_edge[e+3];
        uint2 r0 = s_Hh[(size_t)e0.x * 32 + lane];
        uint2 r1 = s_Hh[(size_t)e1.x * 32 + lane];
        uint2 r2 = s_Hh[(size_t)e2.x * 32 + lane];
        uint2 r3 = s_Hh[(size_t)e3.x * 32 + lane];
        float c0 = __int_as_float(e0.y), c1 = __int_as_float(e1.y);
        float c2 = __int_as_float(e2.y), c3 = __int_as_float(e3.y);
        float2 a01, a23;
        a01 = __half22float2(*(__half2*)&r0.x); a23 = __half22float2(*(__half2*)&r0.y);
        acc.x = fmaf(a01.x, c0, acc.x); acc.y = fmaf(a01.y, c0, acc.y);
        acc.z = fmaf(a23.x, c0, acc.z); acc.w = fmaf(a23.y, c0, acc.w);
        a01 = __half22float2(*(__half2*)&r1.x); a23 = __half22float2(*(__half2*)&r1.y);
        acc.x = fmaf(a01.x, c1, acc.x); acc.y = fmaf(a01.y, c1, acc.y);
        acc.z = fmaf(a23.x, c1, acc.z); acc.w = fmaf(a23.y, c1, acc.w);
        a01 = __half22float2(*(__half2*)&r2.x); a23 = __half22float2(*(__half2*)&r2.y);
        acc.x = fmaf(a01.x, c2, acc.x); acc.y = fmaf(a01.y, c2, acc.y);
        acc.z = fmaf(a23.x, c2, acc.z); acc.w = fmaf(a23.y, c2, acc.w);
        a01 = __half22float2(*(__half2*)&r3.x); a23 = __half22float2(*(__half2*)&r3.y);
        acc.x = fmaf(a01.x, c3, acc.x); acc.y = fmaf(a01.y, c3, acc.y);
        acc.z = fmaf(a23.x, c3, acc.z); acc.w = fmaf(a23.y, c3, acc.w);
    }
    for (; e < end; e++) {
        int2 ec = s_edge[e];
        float c = __int_as_float(ec.y);
        uint2 r0 = s_Hh[(size_t)ec.x * 32 + lane];
        float2 a01 = __half22float2(*(__half2*)&r0.x);
        float2 a23 = __half22float2(*(__half2*)&r0.y);
        acc.x = fmaf(a01.x, c, acc.x); acc.y = fmaf(a01.y, c, acc.y);
        acc.z = fmaf(a23.x, c, acc.z); acc.w = fmaf(a23.y, c, acc.w);
    }
    return acc;
}

// ============ mid-layer aggregation: relu + write fp16 ============
template<int DST>
__global__ void agg_k(const float* __restrict__ b) {
    int node = blockIdx.x * 8 + (threadIdx.x >> 5);
    int lane = threadIdx.x & 31;
    if (node >= NN) return;
    uint2* OUT = (DST == 0) ? s_P0h : s_P1h;

    float4 acc = agg_body(node, lane, b);

    __half2 o0 = __floats2half2_rn(fmaxf(acc.x, 0.f), fmaxf(acc.y, 0.f));
    __half2 o1 = __floats2half2_rn(fmaxf(acc.z, 0.f), fmaxf(acc.w, 0.f));
    uint2 o;
    o.x = *(unsigned*)&o0;
    o.y = *(unsigned*)&o1;
    OUT[(size_t)node * 32 + lane] = o;
}

// ============ FINAL aggregation: relu + dot(Wfc) + atomic pool ============
__global__ void agg_pool_k(const float* __restrict__ b,
                           const float* __restrict__ Wfc,
                           const int* __restrict__ batch) {
    int node = blockIdx.x * 8 + (threadIdx.x >> 5);
    int lane = threadIdx.x & 31;
    if (node >= NN) return;

    float4 acc = agg_body(node, lane, b);

    float4 w = *(const float4*)(Wfc + lane * 4);
    float dot = fmaxf(acc.x, 0.f) * w.x + fmaxf(acc.y, 0.f) * w.y
              + fmaxf(acc.z, 0.f) * w.z + fmaxf(acc.w, 0.f) * w.w;
    #pragma unroll
    for (int o = 16; o; o >>= 1) dot += __shfl_xor_sync(0xffffffffu, dot, o);
    if (lane == 0) atomicAdd(&s_gacc[batch[node]], dot);
}

// ============ finalize: out[g] = gacc[g]/cnt(g) + bfc ============
__global__ void final_k(const int* __restrict__ batch,
                        const float* __restrict__ bfc,
                        float* __restrict__ out) {
    int g = threadIdx.x;
    if (g >= NG) return;
    // count nodes in graph g via two binary searches on sorted batch
    int lo0 = 0, hi0 = NN;
    while (lo0 < hi0) { int m = (lo0 + hi0) >> 1; if (batch[m] < g) lo0 = m + 1; else hi0 = m; }
    int lo1 = lo0, hi1 = NN;
    while (lo1 < hi1) { int m = (lo1 + hi1) >> 1; if (batch[m] < g + 1) lo1 = m + 1; else hi1 = m; }
    float cnt = (float)(lo1 - lo0);
    out[g] = s_gacc[g] / fmaxf(cnt, 1.0f) + bfc[0];
}

extern "C" void kernel_launch(void* const* d_in, const int* in_sizes, int n_in,
                              void* d_out, int out_size) {
    const float* x   = (const float*)d_in[0];
    const int*   ei  = (const int*)d_in[1];    // int32 [2, E]
    const int*   bat = (const int*)d_in[2];    // int32 [N]
    const float* W1  = (const float*)d_in[3];
    const float* b1  = (const float*)d_in[4];
    const float* W2  = (const float*)d_in[5];
    const float* b2  = (const float*)d_in[6];
    const float* Wfc = (const float*)d_in[7];
    const float* bfc = (const float*)d_in[8];
    float*       out = (float*)d_out;

    __half *W1h, *W2h;
    cudaGetSymbolAddress((void**)&W1h, s_W1h);
    cudaGetSymbolAddress((void**)&W2h, s_W2h);

    const int T = 256;
    const int NB_N = (NN + T - 1) / T;
    const int NB_E = (EE + T - 1) / T;
    const int GB   = (NN + 63) / 64;
    const int AB   = (NN + 7) / 8;

    // prologue
    init_k <<<NB_N, T>>>(W1, W2);
    deg_k  <<<NB_E, T>>>(ei);
    scanf_k<<<NBK, SB>>>();
    build_k<<<NB_E, T>>>(ei);

    // 4 GCN layers; final agg fused with pooling+FC dot
    gemm_tc_k<0><<<GB, 256>>>(x, W1h);  agg_k<0><<<AB, T>>>(b1);          // x   -> P0h
    gemm_tc_k<1><<<GB, 256>>>(x, W2h);  agg_k<1><<<AB, T>>>(b2);          // P0h -> P1h
    gemm_tc_k<2><<<GB, 256>>>(x, W2h);  agg_k<0><<<AB, T>>>(b2);          // P1h -> P0h
    gemm_tc_k<1><<<GB, 256>>>(x, W2h);  agg_pool_k<<<AB, T>>>(b2, Wfc, bat); // P0h -> pooled dot

    final_k<<<1, NG>>>(bat, bfc, out);
}

// round 12
// speedup vs baseline: 1.0025x; 1.0025x over previous
#include <cuda_runtime.h>
#include <cuda_fp16.h>
#include <cstdint>

#define NN 50000
#define EE 1600000
#define CC 128
#define NG 128
#define SB 1024
#define NBK ((NN + SB - 1) / SB)   // 49

// ---- scratch (static device globals) ----
__device__ uint4  s_Hh [NN * 16];    // H fp16: 128 halves = 16 uint4 per row
__device__ uint4  s_P0h[NN * 16];    // layer out fp16 (relu applied)
__device__ uint4  s_P1h[NN * 16];
__device__ __half s_W1h[CC * CC];
__device__ __half s_W2h[CC * CC];
__device__ float  s_dinv[NN];
__device__ int    s_deg [NN];
__device__ int    s_rowptr[NN + 1];
__device__ int    s_cursor[NN];
__device__ int    s_csrc [EE];
__device__ float  s_coef [EE];
__device__ int    s_pref [NBK];      // chained-scan prefixes (-1 = not ready)

// ============ init: zero deg + sentinels, convert W ============
__global__ void init_k(const float* __restrict__ W1, const float* __restrict__ W2) {
    int i = blockIdx.x * blockDim.x + threadIdx.x;
    if (i < NN) s_deg[i] = 0;
    if (i < NBK) s_pref[i] = -1;
    if (i < CC * CC) {
        s_W1h[i] = __float2half(W1[i]);
        s_W2h[i] = __float2half(W2[i]);
    }
}

__global__ void deg_k(const int* __restrict__ ei) {
    int e = blockIdx.x * blockDim.x + threadIdx.x;
    if (e < EE) atomicAdd(&s_deg[ei[EE + e]], 1);
}

// ============ fused chained scan: rowptr/cursor/dinv in ONE kernel ============
__global__ void scanf_k() {
    const int tid  = threadIdx.x;
    const int lane = tid & 31;
    const int wid  = tid >> 5;
    const int bid  = blockIdx.x;
    const int i    = bid * SB + tid;
    int v = (i < NN) ? s_deg[i] : 0;

    int x = v;
    #pragma unroll
    for (int o = 1; o < 32; o <<= 1) {
        int t = __shfl_up_sync(0xffffffffu, x, o);
        if (lane >= o) x += t;
    }
    __shared__ int wsum[32];
    if (lane == 31) wsum[wid] = x;
    __syncthreads();
    if (wid == 0) {
        int s = wsum[lane];
        #pragma unroll
        for (int o = 1; o < 32; o <<= 1) {
            int t = __shfl_up_sync(0xffffffffu, s, o);
            if (lane >= o) s += t;
        }
        wsum[lane] = s;
    }
    __syncthreads();
    int incl  = x + (wid ? wsum[wid - 1] : 0);
    int total = wsum[31];

    __shared__ int sprev;
    if (tid == 0) {
        int prev = 0;
        if (bid > 0)
            while ((prev = atomicAdd(&s_pref[bid - 1], 0)) < 0) {}
        sprev = prev;
        __threadfence();
        atomicExch(&s_pref[bid], prev + total);
    }
    __syncthreads();
    int base = sprev;

    if (i < NN) {
        int ex = base + incl - v;
        s_rowptr[i] = ex;
        s_cursor[i] = ex;
        s_dinv[i]   = rsqrtf((float)s_deg[i] + 1.0f);
    }
    if (i == 0) s_rowptr[NN] = EE;
}

// counting-sort by dst (separate src/coef arrays — R9-proven layout)
__global__ void build_k(const int* __restrict__ ei) {
    int e = blockIdx.x * blockDim.x + threadIdx.x;
    if (e >= EE) return;
    int src = ei[e];
    int dst = ei[EE + e];
    int slot = atomicAdd(&s_cursor[dst], 1);
    s_csrc[slot] = src;
    s_coef[slot] = s_dinv[src] * s_dinv[dst];
}

// ============ tensor-core GEMM: H(fp16) = A @ W ============
__device__ __forceinline__ unsigned swz(unsigned row, unsigned col_half) {
    unsigned b = row * 256u + col_half * 2u;
    return b ^ ((row & 7u) << 4);
}

template<int SRC>
__global__ void __launch_bounds__(256) gemm_tc_k(const float* __restrict__ X,
                                                 const __half* __restrict__ Wh) {
    __shared__ __align__(16) unsigned char smem[49152];   // A: 16KB, W: 32KB
    const unsigned sb  = (unsigned)__cvta_generic_to_shared(smem);
    const unsigned sbA = sb;
    const unsigned sbW = sb + 16384u;
    const int tid  = threadIdx.x;
    const int row0 = blockIdx.x * 64;

    if (SRC == 0) {
        #pragma unroll
        for (int it = 0; it < 4; it++) {
            int idx = it * 256 + tid;
            int r   = idx >> 4;
            int c16 = idx & 15;
            int gr  = row0 + r;
            uint4 o;
            if (gr < NN) {
                const float4* p = (const float4*)(X + (size_t)gr * CC + c16 * 8);
                float4 f0 = p[0], f1 = p[1];
                __half2 h0 = __floats2half2_rn(f0.x, f0.y);
                __half2 h1 = __floats2half2_rn(f0.z, f0.w);
                __half2 h2 = __floats2half2_rn(f1.x, f1.y);
                __half2 h3 = __floats2half2_rn(f1.z, f1.w);
                o.x = *(unsigned*)&h0; o.y = *(unsigned*)&h1;
                o.z = *(unsigned*)&h2; o.w = *(unsigned*)&h3;
            } else {
                o = make_uint4(0u, 0u, 0u, 0u);
            }
            *(uint4*)(smem + swz((unsigned)r, (unsigned)(c16 * 8))) = o;
        }
    } else {
        const __half* P = (SRC == 1) ? (const __half*)s_P0h : (const __half*)s_P1h;
        #pragma unroll
        for (int it = 0; it < 4; it++) {
            int idx = it * 256 + tid;
            int r   = idx >> 4;
            int c16 = idx & 15;
            int gr  = row0 + r;
            uint4 o = make_uint4(0u, 0u, 0u, 0u);
            if (gr < NN) o = *(const uint4*)(P + (size_t)gr * CC + c16 * 8);
            *(uint4*)(smem + swz((unsigned)r, (unsigned)(c16 * 8))) = o;
        }
    }
    #pragma unroll
    for (int it = 0; it < 8; it++) {
        int idx = it * 256 + tid;
        int r   = idx >> 4;
        int c16 = idx & 15;
        uint4 o = *(const uint4*)(Wh + (size_t)r * CC + c16 * 8);
        *(uint4*)(smem + 16384 + swz((unsigned)r, (unsigned)(c16 * 8))) = o;
    }
    __syncthreads();

    const int warp   = tid >> 5;
    const int lane   = tid & 31;
    const int warp_m = warp & 3;
    const int warp_n = warp >> 2;
    const int rloc   = warp_m * 16;
    const int c0     = warp_n * 64;

    float d[8][4];
    #pragma unroll
    for (int i = 0; i < 8; i++)
        #pragma unroll
        for (int j = 0; j < 4; j++) d[i][j] = 0.f;

    const int fr = (lane & 7) + ((lane >> 3) & 1) * 8;
    const int fc = (lane >> 4) * 8;

    #pragma unroll
    for (int ks = 0; ks < 8; ks++) {
        const int k0 = ks * 16;
        unsigned a0, a1, a2, a3;
        {
            unsigned addrA = sbA + swz((unsigned)(rloc + fr), (unsigned)(k0 + fc));
            asm volatile("ldmatrix.sync.aligned.m8n8.x4.shared.b16 {%0,%1,%2,%3}, [%4];"
                         : "=r"(a0), "=r"(a1), "=r"(a2), "=r"(a3) : "r"(addrA));
        }
        #pragma unroll
        for (int q = 0; q < 4; q++) {
            int n0 = c0 + q * 16;
            unsigned b0, b1, b2, b3;
            unsigned addrB = sbW + swz((unsigned)(k0 + fr), (unsigned)(n0 + fc));
            asm volatile("ldmatrix.sync.aligned.m8n8.x4.trans.shared.b16 {%0,%1,%2,%3}, [%4];"
                         : "=r"(b0), "=r"(b1), "=r"(b2), "=r"(b3) : "r"(addrB));
            asm volatile("mma.sync.aligned.m16n8k16.row.col.f32.f16.f16.f32 "
                         "{%0,%1,%2,%3}, {%4,%5,%6,%7}, {%8,%9}, {%0,%1,%2,%3};"
                         : "+f"(d[q*2][0]), "+f"(d[q*2][1]), "+f"(d[q*2][2]), "+f"(d[q*2][3])
                         : "r"(a0), "r"(a1), "r"(a2), "r"(a3), "r"(b0), "r"(b1));
            asm volatile("mma.sync.aligned.m16n8k16.row.col.f32.f16.f16.f32 "
                         "{%0,%1,%2,%3}, {%4,%5,%6,%7}, {%8,%9}, {%0,%1,%2,%3};"
                         : "+f"(d[q*2+1][0]), "+f"(d[q*2+1][1]), "+f"(d[q*2+1][2]), "+f"(d[q*2+1][3])
                         : "r"(a0), "r"(a1), "r"(a2), "r"(a3), "r"(b2), "r"(b3));
        }
    }

    __half* H = (__half*)s_Hh;
    const int g  = lane >> 2;
    const int cq = (lane & 3) * 2;
    const int ra = row0 + rloc + g;
    const int rb = ra + 8;
    #pragma unroll
    for (int nt = 0; nt < 8; nt++) {
        int col = c0 + nt * 8 + cq;
        if (ra < NN) *(__half2*)(H + (size_t)ra * CC + col) = __floats2half2_rn(d[nt][0], d[nt][1]);
        if (rb < NN) *(__half2*)(H + (size_t)rb * CC + col) = __floats2half2_rn(d[nt][2], d[nt][3]);
    }
}

// ============ aggregation: 2 edges/warp via half-warps, uint4 rows ============
// lanes 0-15 handle even CSR slots, lanes 16-31 odd; each lane covers 8 channels.
// OUT[i] = relu( sum_e H[src]*coef + H[i]*dinv^2 + b )
template<int DST>
__global__ void agg_k(const float* __restrict__ b) {
    int node   = blockIdx.x * 8 + (threadIdx.x >> 5);
    int lane   = threadIdx.x & 31;
    int half   = lane >> 4;          // 0 or 1
    int lane16 = lane & 15;          // channel group: 8 halves
    if (node >= NN) return;
    uint4* OUT = (DST == 0) ? s_P0h : s_P1h;

    float acc[8];
    // self-loop + bias only in half 0 (counted once)
    if (half == 0) {
        float di = s_dinv[node];
        float sc = di * di;
        uint4 hs = s_Hh[(size_t)node * 16 + lane16];
        float2 q0 = __half22float2(*(__half2*)&hs.x);
        float2 q1 = __half22float2(*(__half2*)&hs.y);
        float2 q2 = __half22float2(*(__half2*)&hs.z);
        float2 q3 = __half22float2(*(__half2*)&hs.w);
        const float4* b4 = (const float4*)(b + lane16 * 8);
        float4 bv0 = b4[0], bv1 = b4[1];
        acc[0] = fmaf(q0.x, sc, bv0.x); acc[1] = fmaf(q0.y, sc, bv0.y);
        acc[2] = fmaf(q1.x, sc, bv0.z); acc[3] = fmaf(q1.y, sc, bv0.w);
        acc[4] = fmaf(q2.x, sc, bv1.x); acc[5] = fmaf(q2.y, sc, bv1.y);
        acc[6] = fmaf(q3.x, sc, bv1.z); acc[7] = fmaf(q3.y, sc, bv1.w);
    } else {
        #pragma unroll
        for (int j = 0; j < 8; j++) acc[j] = 0.f;
    }

    const int beg = s_rowptr[node];
    const int end = s_rowptr[node + 1];
    // unroll 2 per half-warp: 4 rows in flight per warp
    int e = beg + half;
    for (; e + 2 < end; e += 4) {
        int   i0 = s_csrc[e],  i1 = s_csrc[e + 2];
        float c0 = s_coef[e],  c1 = s_coef[e + 2];
        uint4 r0 = s_Hh[(size_t)i0 * 16 + lane16];
        uint4 r1 = s_Hh[(size_t)i1 * 16 + lane16];
        float2 p0, p1, p2, p3;
        p0 = __half22float2(*(__half2*)&r0.x); p1 = __half22float2(*(__half2*)&r0.y);
        p2 = __half22float2(*(__half2*)&r0.z); p3 = __half22float2(*(__half2*)&r0.w);
        acc[0] = fmaf(p0.x, c0, acc[0]); acc[1] = fmaf(p0.y, c0, acc[1]);
        acc[2] = fmaf(p1.x, c0, acc[2]); acc[3] = fmaf(p1.y, c0, acc[3]);
        acc[4] = fmaf(p2.x, c0, acc[4]); acc[5] = fmaf(p2.y, c0, acc[5]);
        acc[6] = fmaf(p3.x, c0, acc[6]); acc[7] = fmaf(p3.y, c0, acc[7]);
        p0 = __half22float2(*(__half2*)&r1.x); p1 = __half22float2(*(__half2*)&r1.y);
        p2 = __half22float2(*(__half2*)&r1.z); p3 = __half22float2(*(__half2*)&r1.w);
        acc[0] = fmaf(p0.x, c1, acc[0]); acc[1] = fmaf(p0.y, c1, acc[1]);
        acc[2] = fmaf(p1.x, c1, acc[2]); acc[3] = fmaf(p1.y, c1, acc[3]);
        acc[4] = fmaf(p2.x, c1, acc[4]); acc[5] = fmaf(p2.y, c1, acc[5]);
        acc[6] = fmaf(p3.x, c1, acc[6]); acc[7] = fmaf(p3.y, c1, acc[7]);
    }
    if (e < end) {
        int   i0 = s_csrc[e];
        float c0 = s_coef[e];
        uint4 r0 = s_Hh[(size_t)i0 * 16 + lane16];
        float2 p0 = __half22float2(*(__half2*)&r0.x);
        float2 p1 = __half22float2(*(__half2*)&r0.y);
        float2 p2 = __half22float2(*(__half2*)&r0.z);
        float2 p3 = __half22float2(*(__half2*)&r0.w);
        acc[0] = fmaf(p0.x, c0, acc[0]); acc[1] = fmaf(p0.y, c0, acc[1]);
        acc[2] = fmaf(p1.x, c0, acc[2]); acc[3] = fmaf(p1.y, c0, acc[3]);
        acc[4] = fmaf(p2.x, c0, acc[4]); acc[5] = fmaf(p2.y, c0, acc[5]);
        acc[6] = fmaf(p3.x, c0, acc[6]); acc[7] = fmaf(p3.y, c0, acc[7]);
    }

    // combine the two half-warps (same channels, disjoint edges)
    #pragma unroll
    for (int j = 0; j < 8; j++)
        acc[j] += __shfl_xor_sync(0xffffffffu, acc[j], 16);

    if (half == 0) {
        __half2 o0 = __floats2half2_rn(fmaxf(acc[0], 0.f), fmaxf(acc[1], 0.f));
        __half2 o1 = __floats2half2_rn(fmaxf(acc[2], 0.f), fmaxf(acc[3], 0.f));
        __half2 o2 = __floats2half2_rn(fmaxf(acc[4], 0.f), fmaxf(acc[5], 0.f));
        __half2 o3 = __floats2half2_rn(fmaxf(acc[6], 0.f), fmaxf(acc[7], 0.f));
        uint4 o;
        o.x = *(unsigned*)&o0; o.y = *(unsigned*)&o1;
        o.z = *(unsigned*)&o2; o.w = *(unsigned*)&o3;
        OUT[(size_t)node * 16 + lane16] = o;
    }
}

// ============ mean-pool (batch sorted) + FC (R9-proven) ============
__global__ void poolfc_k(const int* __restrict__ batch,
                         const float* __restrict__ Wfc,
                         const float* __restrict__ bfc,
                         float* __restrict__ out) {
    int g = blockIdx.x;
    int t = threadIdx.x;
    __shared__ int sb2[2];
    if (t < 2) {
        int key = g + t;
        int lo = 0, hi = NN;
        while (lo < hi) {
            int mid = (lo + hi) >> 1;
            if (batch[mid] < key) lo = mid + 1; else hi = mid;
        }
        sb2[t] = lo;
    }
    __syncthreads();
    const int beg = sb2[0], end = sb2[1];

    const __half* A = (const __half*)s_P1h;
    float s = 0.f;
    for (int r = beg; r < end; r++)
        s += __half2float(A[(size_t)r * CC + t]);

    float v = s * Wfc[t];
    #pragma unroll
    for (int o = 16; o; o >>= 1) v += __shfl_xor_sync(0xffffffffu, v, o);
    __shared__ float sred[4];
    if ((t & 31) == 0) sred[t >> 5] = v;
    __syncthreads();
    if (t == 0) {
        float total = sred[0] + sred[1] + sred[2] + sred[3];
        out[g] = total / fmaxf((float)(end - beg), 1.0f) + bfc[0];
    }
}

extern "C" void kernel_launch(void* const* d_in, const int* in_sizes, int n_in,
                              void* d_out, int out_size) {
    const float* x   = (const float*)d_in[0];
    const int*   ei  = (const int*)d_in[1];    // int32 [2, E]
    const int*   bat = (const int*)d_in[2];    // int32 [N]
    const float* W1  = (const float*)d_in[3];
    const float* b1  = (const float*)d_in[4];
    const float* W2  = (const float*)d_in[5];
    const float* b2  = (const float*)d_in[6];
    const float* Wfc = (const float*)d_in[7];
    const float* bfc = (const float*)d_in[8];
    float*       out = (float*)d_out;

    __half *W1h, *W2h;
    cudaGetSymbolAddress((void**)&W1h, s_W1h);
    cudaGetSymbolAddress((void**)&W2h, s_W2h);

    const int T = 256;
    const int NB_N = (NN + T - 1) / T;
    const int NB_E = (EE + T - 1) / T;
    const int GB   = (NN + 63) / 64;
    const int AB   = (NN + 7) / 8;

    // prologue
    init_k <<<NB_N, T>>>(W1, W2);
    deg_k  <<<NB_E, T>>>(ei);
    scanf_k<<<NBK, SB>>>();
    build_k<<<NB_E, T>>>(ei);

    // 4 GCN layers
    gemm_tc_k<0><<<GB, 256>>>(x, W1h);  agg_k<0><<<AB, T>>>(b1);   // x   -> P0h
    gemm_tc_k<1><<<GB, 256>>>(x, W2h);  agg_k<1><<<AB, T>>>(b2);   // P0h -> P1h
    gemm_tc_k<2><<<GB, 256>>>(x, W2h);  agg_k<0><<<AB, T>>>(b2);   // P1h -> P0h
    gemm_tc_k<1><<<GB, 256>>>(x, W2h);  agg_k<1><<<AB, T>>>(b2);   // P0h -> P1h

    // pool + fc
    poolfc_k<<<NG, CC>>>(bat, Wfc, bfc, out);
}

// round 13
// speedup vs baseline: 1.0711x; 1.0684x over previous
#include <cuda_runtime.h>
#include <cuda_fp16.h>
#include <cstdint>

#define NN 50000
#define EE 1600000
#define CC 128
#define NG 128
#define SB 1024
#define NBK ((NN + SB - 1) / SB)

// ---- scratch (static device globals) ----
__device__ uint2  s_Hh [NN * 32];    // H  fp16: 128 halves/row
__device__ uint2  s_P0h[NN * 32];    // layer out fp16 (relu applied)
__device__ uint2  s_P1h[NN * 32];
__device__ __half s_W1h[CC * CC];
__device__ __half s_W2h[CC * CC];
__device__ float  s_dinv[NN];
__device__ int    s_deg [NN];
__device__ int    s_rowptr[NN + 1];
__device__ int    s_cursor[NN];
__device__ int    s_csrc [EE];
__device__ float  s_coef [EE];
__device__ int    s_bsum[64];
__device__ int    s_boff[64];
__device__ float  s_gacc[NG];        // pooled dot accumulators

// ============ prologue ============
__global__ void zero_deg_k() {
    int i = blockIdx.x * blockDim.x + threadIdx.x;
    if (i < NN) s_deg[i] = 0;
    if (i < NG) s_gacc[i] = 0.f;
}

__global__ void deg_k(const int* __restrict__ ei) {
    int e = blockIdx.x * blockDim.x + threadIdx.x;
    if (e < EE) {
        int dst = ei[EE + e];
        dst = min(max(dst, 0), NN - 1);
        atomicAdd(&s_deg[dst], 1);
    }
}

__global__ void scan1_k() {
    const int tid  = threadIdx.x;
    const int lane = tid & 31;
    const int wid  = tid >> 5;
    const int i    = blockIdx.x * SB + tid;
    int v = (i < NN) ? s_deg[i] : 0;
    int x = v;
    #pragma unroll
    for (int o = 1; o < 32; o <<= 1) {
        int t = __shfl_up_sync(0xffffffffu, x, o);
        if (lane >= o) x += t;
    }
    __shared__ int wsum[32];
    if (lane == 31) wsum[wid] = x;
    __syncthreads();
    if (wid == 0) {
        int s = wsum[lane];
        #pragma unroll
        for (int o = 1; o < 32; o <<= 1) {
            int t = __shfl_up_sync(0xffffffffu, s, o);
            if (lane >= o) s += t;
        }
        wsum[lane] = s;
    }
    __syncthreads();
    int incl = x + (wid ? wsum[wid - 1] : 0);
    if (i < NN) s_rowptr[i] = incl - v;
    if (tid == SB - 1) s_bsum[blockIdx.x] = incl;
}

__global__ void scan2_k() {
    __shared__ int sh[64];
    int t = threadIdx.x;
    int v = (t < NBK) ? s_bsum[t] : 0;
    sh[t] = v;
    __syncthreads();
    for (int o = 1; o < 64; o <<= 1) {
        int u = (t >= o) ? sh[t - o] : 0;
        __syncthreads();
        sh[t] += u;
        __syncthreads();
    }
    s_boff[t] = sh[t] - v;
}

__global__ void scan3_k() {
    int i = blockIdx.x * SB + threadIdx.x;
    if (i < NN) {
        int ex = s_rowptr[i] + s_boff[blockIdx.x];
        s_rowptr[i] = ex;
        s_cursor[i] = ex;
        s_dinv[i]   = rsqrtf((float)s_deg[i] + 1.0f);
    }
    if (i == 0) s_rowptr[NN] = EE;
}

__global__ void build_k(const int* __restrict__ ei) {
    int e = blockIdx.x * blockDim.x + threadIdx.x;
    if (e >= EE) return;
    int src = ei[e];
    int dst = ei[EE + e];
    src = min(max(src, 0), NN - 1);
    dst = min(max(dst, 0), NN - 1);
    int slot = atomicAdd(&s_cursor[dst], 1);
    slot = min(max(slot, 0), EE - 1);
    s_csrc[slot] = src;
    s_coef[slot] = s_dinv[src] * s_dinv[dst];
}

// convert both weight matrices to fp16 once
__global__ void wconv_k(const float* __restrict__ W1, const float* __restrict__ W2) {
    int i = blockIdx.x * blockDim.x + threadIdx.x;
    if (i < CC * CC) {
        s_W1h[i] = __float2half(W1[i]);
        s_W2h[i] = __float2half(W2[i]);
    }
}

// ============ tensor-core GEMM: H(fp16) = A @ W ============
__device__ __forceinline__ unsigned swz(unsigned row, unsigned col_half) {
    unsigned b = row * 256u + col_half * 2u;
    return b ^ ((row & 7u) << 4);
}

template<int SRC>
__global__ void __launch_bounds__(256) gemm_tc_k(const float* __restrict__ X,
                                                 const __half* __restrict__ Wh) {
    __shared__ __align__(16) unsigned char smem[49152];   // A: 16KB, W: 32KB
    const unsigned sb  = (unsigned)__cvta_generic_to_shared(smem);
    const unsigned sbA = sb;
    const unsigned sbW = sb + 16384u;
    const int tid  = threadIdx.x;
    const int row0 = blockIdx.x * 64;

    if (SRC == 0) {
        #pragma unroll
        for (int it = 0; it < 4; it++) {
            int idx = it * 256 + tid;
            int r   = idx >> 4;
            int c16 = idx & 15;
            int gr  = row0 + r;
            uint4 o;
            if (gr < NN) {
                const float4* p = (const float4*)(X + (size_t)gr * CC + c16 * 8);
                float4 f0 = p[0], f1 = p[1];
                __half2 h0 = __floats2half2_rn(f0.x, f0.y);
                __half2 h1 = __floats2half2_rn(f0.z, f0.w);
                __half2 h2 = __floats2half2_rn(f1.x, f1.y);
                __half2 h3 = __floats2half2_rn(f1.z, f1.w);
                o.x = *(unsigned*)&h0; o.y = *(unsigned*)&h1;
                o.z = *(unsigned*)&h2; o.w = *(unsigned*)&h3;
            } else {
                o = make_uint4(0u, 0u, 0u, 0u);
            }
            *(uint4*)(smem + swz((unsigned)r, (unsigned)(c16 * 8))) = o;
        }
    } else {
        const __half* P = (SRC == 1) ? (const __half*)s_P0h : (const __half*)s_P1h;
        #pragma unroll
        for (int it = 0; it < 4; it++) {
            int idx = it * 256 + tid;
            int r   = idx >> 4;
            int c16 = idx & 15;
            int gr  = row0 + r;
            uint4 o = make_uint4(0u, 0u, 0u, 0u);
            if (gr < NN) o = *(const uint4*)(P + (size_t)gr * CC + c16 * 8);
            *(uint4*)(smem + swz((unsigned)r, (unsigned)(c16 * 8))) = o;
        }
    }
    #pragma unroll
    for (int it = 0; it < 8; it++) {
        int idx = it * 256 + tid;
        int r   = idx >> 4;
        int c16 = idx & 15;
        uint4 o = *(const uint4*)(Wh + (size_t)r * CC + c16 * 8);
        *(uint4*)(smem + 16384 + swz((unsigned)r, (unsigned)(c16 * 8))) = o;
    }
    __syncthreads();

    const int warp   = tid >> 5;
    const int lane   = tid & 31;
    const int warp_m = warp & 3;
    const int warp_n = warp >> 2;
    const int rloc   = warp_m * 16;
    const int c0     = warp_n * 64;

    float d[8][4];
    #pragma unroll
    for (int i = 0; i < 8; i++)
        #pragma unroll
        for (int j = 0; j < 4; j++) d[i][j] = 0.f;

    const int fr = (lane & 7) + ((lane >> 3) & 1) * 8;
    const int fc = (lane >> 4) * 8;

    #pragma unroll
    for (int ks = 0; ks < 8; ks++) {
        const int k0 = ks * 16;
        unsigned a0, a1, a2, a3;
        {
            unsigned addrA = sbA + swz((unsigned)(rloc + fr), (unsigned)(k0 + fc));
            asm volatile("ldmatrix.sync.aligned.m8n8.x4.shared.b16 {%0,%1,%2,%3}, [%4];"
                         : "=r"(a0), "=r"(a1), "=r"(a2), "=r"(a3) : "r"(addrA));
        }
        #pragma unroll
        for (int q = 0; q < 4; q++) {
            int n0 = c0 + q * 16;
            unsigned b0, b1, b2, b3;
            unsigned addrB = sbW + swz((unsigned)(k0 + fr), (unsigned)(n0 + fc));
            asm volatile("ldmatrix.sync.aligned.m8n8.x4.trans.shared.b16 {%0,%1,%2,%3}, [%4];"
                         : "=r"(b0), "=r"(b1), "=r"(b2), "=r"(b3) : "r"(addrB));
            asm volatile("mma.sync.aligned.m16n8k16.row.col.f32.f16.f16.f32 "
                         "{%0,%1,%2,%3}, {%4,%5,%6,%7}, {%8,%9}, {%0,%1,%2,%3};"
                         : "+f"(d[q*2][0]), "+f"(d[q*2][1]), "+f"(d[q*2][2]), "+f"(d[q*2][3])
                         : "r"(a0), "r"(a1), "r"(a2), "r"(a3), "r"(b0), "r"(b1));
            asm volatile("mma.sync.aligned.m16n8k16.row.col.f32.f16.f16.f32 "
                         "{%0,%1,%2,%3}, {%4,%5,%6,%7}, {%8,%9}, {%0,%1,%2,%3};"
                         : "+f"(d[q*2+1][0]), "+f"(d[q*2+1][1]), "+f"(d[q*2+1][2]), "+f"(d[q*2+1][3])
                         : "r"(a0), "r"(a1), "r"(a2), "r"(a3), "r"(b2), "r"(b3));
        }
    }

    __half* H = (__half*)s_Hh;
    const int g  = lane >> 2;
    const int cq = (lane & 3) * 2;
    const int ra = row0 + rloc + g;
    const int rb = ra + 8;
    #pragma unroll
    for (int nt = 0; nt < 8; nt++) {
        int col = c0 + nt * 8 + cq;
        if (ra < NN) *(__half2*)(H + (size_t)ra * CC + col) = __floats2half2_rn(d[nt][0], d[nt][1]);
        if (rb < NN) *(__half2*)(H + (size_t)rb * CC + col) = __floats2half2_rn(d[nt][2], d[nt][3]);
    }
}

// ============ aggregation (R9-exact loop): gather fp16, fp32 acc ============
template<int DST>
__global__ void agg_k(const float* __restrict__ b) {
    int node = blockIdx.x * 8 + (threadIdx.x >> 5);
    int lane = threadIdx.x & 31;
    if (node >= NN) return;
    uint2* OUT = (DST == 0) ? s_P0h : s_P1h;

    float di = s_dinv[node];
    float sc = di * di;

    uint2 hs = s_Hh[(size_t)node * 32 + lane];
    float2 h01 = __half22float2(*(__half2*)&hs.x);
    float2 h23 = __half22float2(*(__half2*)&hs.y);
    float4 acc;
    acc.x = fmaf(h01.x, sc, b[lane * 4 + 0]);
    acc.y = fmaf(h01.y, sc, b[lane * 4 + 1]);
    acc.z = fmaf(h23.x, sc, b[lane * 4 + 2]);
    acc.w = fmaf(h23.y, sc, b[lane * 4 + 3]);

    const int beg = s_rowptr[node];
    const int end = s_rowptr[node + 1];
    int e = beg;
    for (; e + 4 <= end; e += 4) {
        int   i0 = s_csrc[e],   i1 = s_csrc[e+1], i2 = s_csrc[e+2], i3 = s_csrc[e+3];
        float c0 = s_coef[e],   c1 = s_coef[e+1], c2 = s_coef[e+2], c3 = s_coef[e+3];
        uint2 r0 = s_Hh[(size_t)i0 * 32 + lane];
        uint2 r1 = s_Hh[(size_t)i1 * 32 + lane];
        uint2 r2 = s_Hh[(size_t)i2 * 32 + lane];
        uint2 r3 = s_Hh[(size_t)i3 * 32 + lane];
        float2 a01, a23;
        a01 = __half22float2(*(__half2*)&r0.x); a23 = __half22float2(*(__half2*)&r0.y);
        acc.x = fmaf(a01.x, c0, acc.x); acc.y = fmaf(a01.y, c0, acc.y);
        acc.z = fmaf(a23.x, c0, acc.z); acc.w = fmaf(a23.y, c0, acc.w);
        a01 = __half22float2(*(__half2*)&r1.x); a23 = __half22float2(*(__half2*)&r1.y);
        acc.x = fmaf(a01.x, c1, acc.x); acc.y = fmaf(a01.y, c1, acc.y);
        acc.z = fmaf(a23.x, c1, acc.z); acc.w = fmaf(a23.y, c1, acc.w);
        a01 = __half22float2(*(__half2*)&r2.x); a23 = __half22float2(*(__half2*)&r2.y);
        acc.x = fmaf(a01.x, c2, acc.x); acc.y = fmaf(a01.y, c2, acc.y);
        acc.z = fmaf(a23.x, c2, acc.z); acc.w = fmaf(a23.y, c2, acc.w);
        a01 = __half22float2(*(__half2*)&r3.x); a23 = __half22float2(*(__half2*)&r3.y);
        acc.x = fmaf(a01.x, c3, acc.x); acc.y = fmaf(a01.y, c3, acc.y);
        acc.z = fmaf(a23.x, c3, acc.z); acc.w = fmaf(a23.y, c3, acc.w);
    }
    for (; e < end; e++) {
        float c0 = s_coef[e];
        uint2 r0 = s_Hh[(size_t)s_csrc[e] * 32 + lane];
        float2 a01 = __half22float2(*(__half2*)&r0.x);
        float2 a23 = __half22float2(*(__half2*)&r0.y);
        acc.x = fmaf(a01.x, c0, acc.x); acc.y = fmaf(a01.y, c0, acc.y);
        acc.z = fmaf(a23.x, c0, acc.z); acc.w = fmaf(a23.y, c0, acc.w);
    }

    __half2 o0 = __floats2half2_rn(fmaxf(acc.x, 0.f), fmaxf(acc.y, 0.f));
    __half2 o1 = __floats2half2_rn(fmaxf(acc.z, 0.f), fmaxf(acc.w, 0.f));
    uint2 o;
    o.x = *(unsigned*)&o0;
    o.y = *(unsigned*)&o1;
    OUT[(size_t)node * 32 + lane] = o;
}

// ============ FINAL aggregation: same gather, epilogue = relu·Wfc dot + pool ============
__global__ void agg_pool_k(const float* __restrict__ b,
                           const float* __restrict__ Wfc,
                           const int* __restrict__ batch) {
    int node = blockIdx.x * 8 + (threadIdx.x >> 5);
    int lane = threadIdx.x & 31;
    if (node >= NN) return;

    float di = s_dinv[node];
    float sc = di * di;

    uint2 hs = s_Hh[(size_t)node * 32 + lane];
    float2 h01 = __half22float2(*(__half2*)&hs.x);
    float2 h23 = __half22float2(*(__half2*)&hs.y);
    float4 acc;
    acc.x = fmaf(h01.x, sc, b[lane * 4 + 0]);
    acc.y = fmaf(h01.y, sc, b[lane * 4 + 1]);
    acc.z = fmaf(h23.x, sc, b[lane * 4 + 2]);
    acc.w = fmaf(h23.y, sc, b[lane * 4 + 3]);

    const int beg = s_rowptr[node];
    const int end = s_rowptr[node + 1];
    int e = beg;
    for (; e + 4 <= end; e += 4) {
        int   i0 = s_csrc[e],   i1 = s_csrc[e+1], i2 = s_csrc[e+2], i3 = s_csrc[e+3];
        float c0 = s_coef[e],   c1 = s_coef[e+1], c2 = s_coef[e+2], c3 = s_coef[e+3];
        uint2 r0 = s_Hh[(size_t)i0 * 32 + lane];
        uint2 r1 = s_Hh[(size_t)i1 * 32 + lane];
        uint2 r2 = s_Hh[(size_t)i2 * 32 + lane];
        uint2 r3 = s_Hh[(size_t)i3 * 32 + lane];
        float2 a01, a23;
        a01 = __half22float2(*(__half2*)&r0.x); a23 = __half22float2(*(__half2*)&r0.y);
        acc.x = fmaf(a01.x, c0, acc.x); acc.y = fmaf(a01.y, c0, acc.y);
        acc.z = fmaf(a23.x, c0, acc.z); acc.w = fmaf(a23.y, c0, acc.w);
        a01 = __half22float2(*(__half2*)&r1.x); a23 = __half22float2(*(__half2*)&r1.y);
        acc.x = fmaf(a01.x, c1, acc.x); acc.y = fmaf(a01.y, c1, acc.y);
        acc.z = fmaf(a23.x, c1, acc.z); acc.w = fmaf(a23.y, c1, acc.w);
        a01 = __half22float2(*(__half2*)&r2.x); a23 = __half22float2(*(__half2*)&r2.y);
        acc.x = fmaf(a01.x, c2, acc.x); acc.y = fmaf(a01.y, c2, acc.y);
        acc.z = fmaf(a23.x, c2, acc.z); acc.w = fmaf(a23.y, c2, acc.w);
        a01 = __half22float2(*(__half2*)&r3.x); a23 = __half22float2(*(__half2*)&r3.y);
        acc.x = fmaf(a01.x, c3, acc.x); acc.y = fmaf(a01.y, c3, acc.y);
        acc.z = fmaf(a23.x, c3, acc.z); acc.w = fmaf(a23.y, c3, acc.w);
    }
    for (; e < end; e++) {
        float c0 = s_coef[e];
        uint2 r0 = s_Hh[(size_t)s_csrc[e] * 32 + lane];
        float2 a01 = __half22float2(*(__half2*)&r0.x);
        float2 a23 = __half22float2(*(__half2*)&r0.y);
        acc.x = fmaf(a01.x, c0, acc.x); acc.y = fmaf(a01.y, c0, acc.y);
        acc.z = fmaf(a23.x, c0, acc.z); acc.w = fmaf(a23.y, c0, acc.w);
    }

    // relu -> dot with Wfc -> warp reduce -> one scalar atomic per node
    float4 w = *(const float4*)(Wfc + lane * 4);
    float dot = fmaxf(acc.x, 0.f) * w.x + fmaxf(acc.y, 0.f) * w.y
              + fmaxf(acc.z, 0.f) * w.z + fmaxf(acc.w, 0.f) * w.w;
    #pragma unroll
    for (int o = 16; o; o >>= 1) dot += __shfl_xor_sync(0xffffffffu, dot, o);
    if (lane == 0) atomicAdd(&s_gacc[batch[node]], dot);
}

// ============ finalize: out[g] = gacc[g]/cnt(g) + bfc ============
__global__ void final_k(const int* __restrict__ batch,
                        const float* __restrict__ bfc,
                        float* __restrict__ out) {
    int g = threadIdx.x;
    if (g >= NG) return;
    int lo0 = 0, hi0 = NN;
    while (lo0 < hi0) { int m = (lo0 + hi0) >> 1; if (batch[m] < g) lo0 = m + 1; else hi0 = m; }
    int lo1 = lo0, hi1 = NN;
    while (lo1 < hi1) { int m = (lo1 + hi1) >> 1; if (batch[m] < g + 1) lo1 = m + 1; else hi1 = m; }
    float cnt = (float)(lo1 - lo0);
    out[g] = s_gacc[g] / fmaxf(cnt, 1.0f) + bfc[0];
}

extern "C" void kernel_launch(void* const* d_in, const int* in_sizes, int n_in,
                              void* d_out, int out_size) {
    const float* x   = (const float*)d_in[0];
    const int*   ei  = (const int*)d_in[1];    // int32 [2, E]
    const int*   bat = (const int*)d_in[2];    // int32 [N]
    const float* W1  = (const float*)d_in[3];
    const float* b1  = (const float*)d_in[4];
    const float* W2  = (const float*)d_in[5];
    const float* b2  = (const float*)d_in[6];
    const float* Wfc = (const float*)d_in[7];
    const float* bfc = (const float*)d_in[8];
    float*       out = (float*)d_out;

    __half *W1h, *W2h;
    cudaGetSymbolAddress((void**)&W1h, s_W1h);
    cudaGetSymbolAddress((void**)&W2h, s_W2h);

    const int T = 256;
    const int NB_N = (NN + T - 1) / T;
    const int NB_E = (EE + T - 1) / T;
    const int GB   = (NN + 63) / 64;
    const int AB   = (NN + 7) / 8;

    // prologue: CSR build + weight conversion (R9-identical)
    zero_deg_k<<<NB_N, T>>>();
    deg_k     <<<NB_E, T>>>(ei);
    scan1_k   <<<NBK, SB>>>();
    scan2_k   <<<1, 64>>>();
    scan3_k   <<<NBK, SB>>>();
    build_k   <<<NB_E, T>>>(ei);
    wconv_k   <<<(CC * CC + T - 1) / T, T>>>(W1, W2);

    // 4 GCN layers; final layer fused with pooling+FC dot
    gemm_tc_k<0><<<GB, 256>>>(x, W1h);  agg_k<0><<<AB, T>>>(b1);            // x   -> P0h
    gemm_tc_k<1><<<GB, 256>>>(x, W2h);  agg_k<1><<<AB, T>>>(b2);            // P0h -> P1h
    gemm_tc_k<2><<<GB, 256>>>(x, W2h);  agg_k<0><<<AB, T>>>(b2);            // P1h -> P0h
    gemm_tc_k<1><<<GB, 256>>>(x, W2h);  agg_pool_k<<<AB, T>>>(b2, Wfc, bat); // P0h -> pooled

    final_k<<<1, NG>>>(bat, bfc, out);
}